// round 10
// baseline (speedup 1.0000x reference)
#include <cuda_runtime.h>
#include <cuda_bf16.h>
#include <cstdint>

#define T_STEPS 1024
#define BATCH   128
#define FEAT    88
#define HID     1024
#define CLS     88
#define KTOT    1112          // HID + FEAT
#define KP      1152          // padded K
#define WS_STRIDE 1160        // resident-W row stride (halfs): 4-word/row shift, LDS64 conflict-free
#define NCTA    128
#define NTHR    256
#define MT      64            // batch rows per CTA
#define UPC     16            // hidden units per CTA -> 64 gate cols
#define CW      128           // A chunk width (K cols)
#define NSEQ    9             // chunks per step (1 x + 8 h)
#define ASTR    136           // A-tile row stride (halfs)
#define NBUF    4             // A-stage ring buffers
#define GSM_STRIDE 68
#define FC_ASTR 72

// ---------------- device globals ----------------
__device__ __nv_bfloat16 g_Wc[(size_t)4096 * KP];
__device__ __nv_bfloat16 g_Wfcb[(size_t)CLS * HID];
__device__ float         g_bsum[4096];
__device__ __nv_bfloat16 g_xb[(size_t)T_STEPS * BATCH * FEAT];
__device__ __nv_bfloat16 g_h[2][BATCH * HID];
__device__ __nv_bfloat16 g_Hall[(size_t)T_STEPS * BATCH * HID];
__device__ int           g_flag[NCTA * 4];

// ---------------- helpers ----------------
__device__ __forceinline__ unsigned smem_u32(const void* p) {
    return (unsigned)__cvta_generic_to_shared(p);
}
__device__ __forceinline__ float sigmoidf_(float x) {
    return 1.0f / (1.0f + __expf(-x));
}
__device__ __forceinline__ float tanhf_(float x) {
    float ax = fabsf(x);
    float e  = __expf(-2.0f * ax);
    float r  = (1.0f - e) / (1.0f + e);
    return (x < 0.0f) ? -r : r;
}

#define MMA_BF16(ACC, A0, A1, A2, A3, B0, B1)                                             \
    asm volatile(                                                                         \
        "mma.sync.aligned.m16n8k16.row.col.f32.bf16.bf16.f32 "                            \
        "{%0,%1,%2,%3}, {%4,%5,%6,%7}, {%8,%9}, {%0,%1,%2,%3};\n"                         \
        : "+f"((ACC)[0]), "+f"((ACC)[1]), "+f"((ACC)[2]), "+f"((ACC)[3])                  \
        : "r"(A0), "r"(A1), "r"(A2), "r"(A3), "r"(B0), "r"(B1))

#define LDMATRIX_X4(R0, R1, R2, R3, ADDR)                                                 \
    asm volatile("ldmatrix.sync.aligned.m8n8.x4.shared.b16 {%0,%1,%2,%3}, [%4];\n"        \
                 : "=r"(R0), "=r"(R1), "=r"(R2), "=r"(R3) : "r"(ADDR))

#define LDS64(R0, R1, ADDR)                                                               \
    asm volatile("ld.shared.v2.u32 {%0,%1}, [%2];" : "=r"(R0), "=r"(R1) : "r"(ADDR))

#define CP_ASYNC16(DST, SRC)                                                              \
    asm volatile("cp.async.cg.shared.global [%0], [%1], 16;\n" :: "r"(DST), "l"(SRC))
#define CP_ASYNC16_ZFILL(DST, SRC)                                                        \
    asm volatile("cp.async.cg.shared.global [%0], [%1], 16, %2;\n"                        \
                 :: "r"(DST), "l"(SRC), "r"(0))
#define CP_COMMIT  asm volatile("cp.async.commit_group;\n")
#define CP_WAIT(N) asm volatile("cp.async.wait_group %0;\n" :: "n"(N))

// ---------------- prep kernels (lstm_kernel stays the 4th launch for ncu) ----------------
__global__ void init_kernel() {
    int idx = blockIdx.x * blockDim.x + threadIdx.x;
    uint4 z = make_uint4(0u, 0u, 0u, 0u);
    for (int i = idx; i < 32768; i += gridDim.x * blockDim.x)
        reinterpret_cast<uint4*>(g_h)[i] = z;
    if (idx < NCTA * 4) g_flag[idx] = 0;
}

__global__ void prep_all_kernel(const float* __restrict__ Wih, const float* __restrict__ Whh,
                                const float* __restrict__ bih, const float* __restrict__ bhh,
                                const float* __restrict__ Wfc) {
    size_t idx = (size_t)blockIdx.x * blockDim.x + threadIdx.x;
    size_t total = (size_t)4096 * KP;
    if (idx < total) {
        int n = (int)(idx / KP);
        int k = (int)(idx % KP);
        float v = 0.0f;
        if (k < HID)        v = Whh[(size_t)n * HID + k];
        else if (k < KTOT)  v = Wih[(size_t)n * FEAT + (k - HID)];
        g_Wc[idx] = __float2bfloat16(v);
    }
    if (idx < 4096) g_bsum[idx] = bih[idx] + bhh[idx];
    if (idx < (size_t)CLS * HID) g_Wfcb[idx] = __float2bfloat16(Wfc[idx]);
}

__global__ void prep_x_kernel(const float* __restrict__ x) {
    size_t idx = (size_t)blockIdx.x * blockDim.x + threadIdx.x;
    size_t total = (size_t)T_STEPS * BATCH * FEAT;
    if (idx < total) g_xb[idx] = __float2bfloat16(x[idx]);
}

// ---------------- persistent LSTM step kernel ----------------
// 128 CTAs, 256 threads (R7 skeleton). CTA (m,n): m = bid&1 (64 batch rows),
// n = bid>>1 (16 units -> 64 gate cols). Half-barrier on 64 same-half flags.
// 9 K-chunks of 128 via cp.async 4-buffer ring (depth 3); gsm aliases buf 1.
// NEW: chunk loop fully unrolled; per 4-ks group all 8 LDSM + 8 LDS64 are
// issued back-to-back (MLP ~16) before the 16 MMAs -> one latency absorption
// per group instead of eight serial ld->mma chains.
__global__ void __launch_bounds__(NTHR, 1)
lstm_kernel(const int* __restrict__ lens)
{
    extern __shared__ char smem_raw[];
    __nv_bfloat16* Ws  = reinterpret_cast<__nv_bfloat16*>(smem_raw);        // 64 * WS_STRIDE
    __nv_bfloat16* As  = Ws + 64 * WS_STRIDE;                               // NBUF * 64 * ASTR
    float* gsm         = reinterpret_cast<float*>(As + 64 * ASTR);          // aliases ring buf 1
    float* bias_s      = reinterpret_cast<float*>(As + NBUF * 64 * ASTR);   // 64
    int*   len_s       = reinterpret_cast<int*>(bias_s + 64);               // 64

    const int tid   = threadIdx.x;
    const int bid   = blockIdx.x;
    const int cta_m = bid & 1;
    const int cta_n = bid >> 1;
    const int b0    = cta_m * MT;
    const int hid0  = cta_n * UPC;

    // resident W slice, k-permuted per 16-half group (pair q <- pair (q>>1)+((q&1)<<2))
    for (int i = tid; i < 64 * (KP / 2); i += NTHR) {
        int n = i / (KP / 2), j = i % (KP / 2);
        int g16 = j >> 3, q = j & 7;
        int sp  = (q >> 1) + ((q & 1) << 2);
        int g = n >> 4, u = n & 15;
        const unsigned* src = reinterpret_cast<const unsigned*>(
                g_Wc + (size_t)(g * HID + hid0 + u) * KP);
        reinterpret_cast<unsigned*>(Ws + (size_t)n * WS_STRIDE)[j] = src[g16 * 8 + sp];
    }
    if (tid < 64) {
        int g = tid >> 4, u = tid & 15;
        bias_s[tid] = g_bsum[g * HID + hid0 + u];
    } else if (tid < 128) {
        len_s[tid - 64] = lens[b0 + (tid - 64)];
    }
    __syncthreads();

    const int lane = tid & 31, wid = tid >> 5;
    const int wm = wid & 1;        // 0..1 : 32 rows
    const int wn = wid >> 1;       // 0..3 : 16 cols
    const int eu  = tid & 15;
    const int eb0 = tid >> 4;

    const unsigned ws_u = smem_u32(Ws);
    const unsigned as_u = smem_u32(As);

    const bool watcher = (tid < 64);
    int* const my_fp   = &g_flag[(((tid & 63) << 1) | cta_m) << 2];

    float hreg[4] = {0.f, 0.f, 0.f, 0.f};
    float creg[4] = {0.f, 0.f, 0.f, 0.f};

    for (int t = 0; t < T_STEPS; ++t) {
        const __nv_bfloat16* __restrict__ h_cur = g_h[t & 1];
        __nv_bfloat16* __restrict__ h_nxt = g_h[(t & 1) ^ 1];

        auto stage = [&](int s) {
            unsigned dstb = as_u + (unsigned)((s & 3) * 64 * ASTR * 2);
#pragma unroll
            for (int r = 0; r < 4; ++r) {
                int slot = tid + r * NTHR;           // 1024 slots = 64 rows x 16 seg
                int row = slot >> 4, c16 = slot & 15;
                unsigned dst = dstb + (unsigned)((row * ASTR + c16 * 8) * 2);
                if (s >= 1) {
                    CP_ASYNC16(dst, h_cur + (size_t)(b0 + row) * HID + (s - 1) * CW + c16 * 8);
                } else {
                    int f = c16 * 8;
                    if (f + 8 <= FEAT) {
                        CP_ASYNC16(dst, g_xb + ((size_t)t * BATCH + b0 + row) * FEAT + f);
                    } else {
                        CP_ASYNC16_ZFILL(dst, g_xb);
                    }
                }
            }
            CP_COMMIT;
        };

        // x chunk is h-independent: stage before the barrier
        stage(0);

        // half-barrier: 64 same-half CTAs have published step t-1
        if (t > 0) {
            int fv = 0x7fffffff;
            if (watcher)
                asm volatile("ld.acquire.gpu.global.b32 %0, [%1];" : "=r"(fv) : "l"(my_fp) : "memory");
            for (;;) {
                if (__syncthreads_count(fv >= t) == NTHR) break;
                if (watcher && fv < t)
                    asm volatile("ld.acquire.gpu.global.b32 %0, [%1];" : "=r"(fv) : "l"(my_fp) : "memory");
            }
        }

        stage(1);
        stage(2);

        float acc[2][2][4];
#pragma unroll
        for (int a = 0; a < 2; ++a)
#pragma unroll
            for (int b = 0; b < 2; ++b)
#pragma unroll
                for (int c = 0; c < 4; ++c) acc[a][b][c] = 0.f;

#pragma unroll
        for (int s = 0; s < NSEQ; ++s) {
            if (s < NSEQ - 2)      { CP_WAIT(2); }
            else if (s == NSEQ - 2){ CP_WAIT(1); }
            else                   { CP_WAIT(0); }
            __syncthreads();
            if (s + 3 < NSEQ) stage(s + 3);

            const int kcol  = (s == 0) ? HID : ((s - 1) * CW);
            const int ksmax = (s == 0) ? 6 : 8;     // x-chunk cols 1120..1151 are pad
            const unsigned abase = as_u + (unsigned)((s & 3) * 64 * ASTR * 2);

#pragma unroll
            for (int kg4 = 0; kg4 < ksmax; kg4 += 4) {
                const int kn = (ksmax - kg4 < 4) ? (ksmax - kg4) : 4;
                unsigned af[4][2][4];
                unsigned bfr[4][2][2];
                // batch: all LDSM for this 4-ks group
#pragma unroll
                for (int k4 = 0; k4 < 4; ++k4) {
                    if (k4 < kn) {
                        const int kk = (kg4 + k4) * 16;
#pragma unroll
                        for (int mi = 0; mi < 2; ++mi) {
                            unsigned addr = abase +
                                (unsigned)(((wm * 32 + mi * 16 + (lane & 15)) * ASTR +
                                            kk + ((lane >> 4) << 3)) * 2);
                            LDMATRIX_X4(af[k4][mi][0], af[k4][mi][1], af[k4][mi][2], af[k4][mi][3], addr);
                        }
                    }
                }
                // batch: all LDS64 B fragments for this group
#pragma unroll
                for (int k4 = 0; k4 < 4; ++k4) {
                    if (k4 < kn) {
                        const int kg = kcol + (kg4 + k4) * 16;
#pragma unroll
                        for (int nf = 0; nf < 2; ++nf) {
                            int n = wn * 16 + nf * 8 + (lane >> 2);
                            unsigned baddr = ws_u +
                                (unsigned)((n * WS_STRIDE + kg) * 2) + ((lane & 3) << 3);
                            LDS64(bfr[k4][nf][0], bfr[k4][nf][1], baddr);
                        }
                    }
                }
                // batch: MMAs (4 independent acc chains)
#pragma unroll
                for (int k4 = 0; k4 < 4; ++k4) {
                    if (k4 < kn) {
#pragma unroll
                        for (int nf = 0; nf < 2; ++nf)
#pragma unroll
                            for (int mi = 0; mi < 2; ++mi)
                                MMA_BF16(acc[mi][nf],
                                         af[k4][mi][0], af[k4][mi][1], af[k4][mi][2], af[k4][mi][3],
                                         bfr[k4][nf][0], bfr[k4][nf][1]);
                    }
                }
            }
        }
        __syncthreads();

        // accumulators -> gsm (aliases ring buf 1; all computes done)
#pragma unroll
        for (int mi = 0; mi < 2; ++mi) {
            int r = wm * 32 + mi * 16 + (lane >> 2);
#pragma unroll
            for (int nf = 0; nf < 2; ++nf) {
                int c = wn * 16 + nf * 8 + ((lane & 3) << 1);
                gsm[r * GSM_STRIDE + c]           = acc[mi][nf][0];
                gsm[r * GSM_STRIDE + c + 1]       = acc[mi][nf][1];
                gsm[(r + 8) * GSM_STRIDE + c]     = acc[mi][nf][2];
                gsm[(r + 8) * GSM_STRIDE + c + 1] = acc[mi][nf][3];
            }
        }
        __syncthreads();

        // LSTM cell: thread owns (b_local = eb0 + 16p, unit = eu)
#pragma unroll
        for (int p = 0; p < 4; ++p) {
            int bl = eb0 + p * 16;
            float gi = gsm[bl * GSM_STRIDE + eu]        + bias_s[eu];
            float gf = gsm[bl * GSM_STRIDE + 16 + eu]   + bias_s[16 + eu];
            float gg = gsm[bl * GSM_STRIDE + 32 + eu]   + bias_s[32 + eu];
            float go = gsm[bl * GSM_STRIDE + 48 + eu]   + bias_s[48 + eu];
            float ii = sigmoidf_(gi);
            float ff = sigmoidf_(gf);
            float gt = tanhf_(gg);
            float oo = sigmoidf_(go);
            float cn = ff * creg[p] + ii * gt;
            float hn = oo * tanhf_(cn);
            bool  m  = t < len_s[bl];
            float h2 = m ? hn : hreg[p];
            creg[p]  = m ? cn : creg[p];
            hreg[p]  = h2;
            h_nxt[(b0 + bl) * HID + hid0 + eu] = __float2bfloat16(h2);
        }

        // publish step t
        __threadfence();
        __syncthreads();
        if (tid == 0)
            asm volatile("st.release.gpu.global.b32 [%0], %1;"
                         :: "l"(&g_flag[bid << 2]), "r"(t + 1) : "memory");

        // g_Hall: no inter-CTA consumer -> off critical path
#pragma unroll
        for (int p = 0; p < 4; ++p) {
            int bl = eb0 + p * 16;
            g_Hall[((size_t)t * BATCH + b0 + bl) * HID + hid0 + eu] =
                __float2bfloat16(hreg[p]);
        }
    }
}

// ---------------- FC head: logits + binary expansion ----------------
__global__ void __launch_bounds__(128)
fc_kernel(const int* __restrict__ lens, const float* __restrict__ bfc,
          float* __restrict__ out)
{
    __shared__ __nv_bfloat16 As[64 * FC_ASTR];
    __shared__ __nv_bfloat16 Bs[88 * FC_ASTR];

    const int tid  = threadIdx.x;
    const int lane = tid & 31, wid = tid >> 5;
    const int r0   = blockIdx.x * 64;   // rows of H_all (tb = t*128 + b)

    float acc[11][4];
#pragma unroll
    for (int i = 0; i < 11; ++i)
#pragma unroll
        for (int j = 0; j < 4; ++j) acc[i][j] = 0.f;

    const unsigned as_u = smem_u32(As);
    const unsigned bs_u = smem_u32(Bs);

    for (int ch = 0; ch < 16; ++ch) {
        __syncthreads();
        const int k0 = ch * 64;
        for (int i = tid; i < 512; i += 128) {
            int row = i >> 3, c8 = i & 7;
            uint4 v = *(reinterpret_cast<const uint4*>(
                    g_Hall + (size_t)(r0 + row) * HID + k0) + c8);
            *(reinterpret_cast<uint4*>(As + row * FC_ASTR) + c8) = v;
        }
        for (int i = tid; i < 704; i += 128) {
            int row = i >> 3, c8 = i & 7;
            uint4 v = *(reinterpret_cast<const uint4*>(
                    g_Wfcb + (size_t)row * HID + k0) + c8);
            *(reinterpret_cast<uint4*>(Bs + row * FC_ASTR) + c8) = v;
        }
        __syncthreads();
#pragma unroll
        for (int ks = 0; ks < 4; ++ks) {
            int kk = ks * 16;
            unsigned a0, a1, a2, a3;
            unsigned addr = as_u +
                (unsigned)(((wid * 16 + (lane & 15)) * FC_ASTR + kk + ((lane >> 4) << 3)) * 2);
            LDMATRIX_X4(a0, a1, a2, a3, addr);
#pragma unroll
            for (int nf = 0; nf < 11; ++nf) {
                int n = nf * 8 + (lane >> 2);
                unsigned baddr = bs_u +
                    (unsigned)((n * FC_ASTR + kk + ((lane & 3) << 1)) * 2);
                unsigned b0r, b1r;
                asm volatile("ld.shared.b32 %0, [%1];" : "=r"(b0r) : "r"(baddr));
                asm volatile("ld.shared.b32 %0, [%1];" : "=r"(b1r) : "r"(baddr + 16));
                MMA_BF16(acc[nf], a0, a1, a2, a3, b0r, b1r);
            }
        }
    }

#pragma unroll
    for (int half = 0; half < 2; ++half) {
        int r  = wid * 16 + (lane >> 2) + half * 8;
        int tb = r0 + r;
        int t  = tb >> 7;
        int b  = tb & 127;
        bool m = t < __ldg(lens + b);
        size_t obase = ((size_t)b * T_STEPS + t) * CLS * 2;
#pragma unroll
        for (int nf = 0; nf < 11; ++nf) {
            int c = nf * 8 + ((lane & 3) << 1);
            float l0 = acc[nf][half * 2 + 0] + __ldg(bfc + c);
            float l1 = acc[nf][half * 2 + 1] + __ldg(bfc + c + 1);
            if (!m) { l0 = 0.f; l1 = 0.f; }
            float4 v = make_float4(l0, 1.f - l0, l1, 1.f - l1);
            *reinterpret_cast<float4*>(out + obase + (size_t)c * 2) = v;
        }
    }
}

// ---------------- launch ----------------
extern "C" void kernel_launch(void* const* d_in, const int* in_sizes, int n_in,
                              void* d_out, int out_size) {
    const float* x    = (const float*)d_in[0];
    const int*   lens = (const int*)d_in[1];    // int32 (JAX x64 disabled)
    const float* Wih  = (const float*)d_in[2];
    const float* Whh  = (const float*)d_in[3];
    const float* bih  = (const float*)d_in[4];
    const float* bhh  = (const float*)d_in[5];
    const float* Wfc  = (const float*)d_in[6];
    const float* bfc  = (const float*)d_in[7];
    float*       out  = (float*)d_out;
    (void)in_sizes; (void)n_in; (void)out_size;

    // lstm_kernel is the 4th launch (ncu capture slot)
    init_kernel<<<64, 256>>>();
    {
        size_t tot = (size_t)4096 * KP;
        prep_all_kernel<<<(unsigned)((tot + 255) / 256), 256>>>(Wih, Whh, bih, bhh, Wfc);
    }
    {
        size_t tot = (size_t)T_STEPS * BATCH * FEAT;
        prep_x_kernel<<<(unsigned)((tot + 255) / 256), 256>>>(x);
    }

    int smem = 64 * WS_STRIDE * 2          // resident W slice   (148480)
             + NBUF * 64 * ASTR * 2        // A-stage ring       (69632; buf1 doubles as gsm)
             + 64 * 4 + 64 * 4;            // bias + lengths
    cudaFuncSetAttribute(lstm_kernel, cudaFuncAttributeMaxDynamicSharedMemorySize, smem);
    lstm_kernel<<<NCTA, NTHR, smem>>>(lens);

    fc_kernel<<<(T_STEPS * BATCH) / 64, 128>>>(lens, bfc, out);
}

// round 12
// speedup vs baseline: 1.0322x; 1.0322x over previous
#include <cuda_runtime.h>
#include <cuda_bf16.h>
#include <cstdint>

#define T_STEPS 1024
#define BATCH   128
#define FEAT    88
#define HID     1024
#define CLS     88
#define NCTA    128
#define NTHR    256
#define MT      64            // batch rows per CTA
#define UPC     16            // hidden units per CTA -> 64 gate cols
#define CW      128           // h chunk width (K cols)
#define WS_STRIDE 1032        // resident-W row stride (halfs): 4-word/row bank shift
#define ASTR    136           // A-tile row stride (halfs)
#define NBUF    4
#define GBSTR   72            // gx-slice row stride (halfs)
#define GSM_STRIDE 68
#define FC_ASTR 72

// ---------------- device globals ----------------
__device__ __nv_bfloat16 g_Wc[(size_t)4096 * HID];                 // bf16 W_hh
__device__ __nv_bfloat16 g_Wxb[(size_t)4096 * 96];                 // bf16 W_ih padded to 96 (zero pad)
__device__ __nv_bfloat16 g_Wfcb[(size_t)CLS * HID];
__device__ float         g_bsum[4096];
__device__ __nv_bfloat16 g_xb[(size_t)T_STEPS * BATCH * FEAT];     // x in bf16
__device__ __nv_bfloat16 g_gx[(size_t)T_STEPS * BATCH * 4096];     // precomputed x@Wih^T + bias
__device__ __nv_bfloat16 g_h[2][BATCH * HID];
__device__ __nv_bfloat16 g_Hall[(size_t)T_STEPS * BATCH * HID];
__device__ int           g_flag[NCTA * 4];

// ---------------- helpers ----------------
__device__ __forceinline__ unsigned smem_u32(const void* p) {
    return (unsigned)__cvta_generic_to_shared(p);
}
__device__ __forceinline__ float sigmoidf_(float x) {
    return 1.0f / (1.0f + __expf(-x));
}
__device__ __forceinline__ float tanhf_(float x) {
    float ax = fabsf(x);
    float e  = __expf(-2.0f * ax);
    float r  = (1.0f - e) / (1.0f + e);
    return (x < 0.0f) ? -r : r;
}

#define MMA_BF16(ACC, A0, A1, A2, A3, B0, B1)                                             \
    asm volatile(                                                                         \
        "mma.sync.aligned.m16n8k16.row.col.f32.bf16.bf16.f32 "                            \
        "{%0,%1,%2,%3}, {%4,%5,%6,%7}, {%8,%9}, {%0,%1,%2,%3};\n"                         \
        : "+f"((ACC)[0]), "+f"((ACC)[1]), "+f"((ACC)[2]), "+f"((ACC)[3])                  \
        : "r"(A0), "r"(A1), "r"(A2), "r"(A3), "r"(B0), "r"(B1))

#define LDMATRIX_X4(R0, R1, R2, R3, ADDR)                                                 \
    asm volatile("ldmatrix.sync.aligned.m8n8.x4.shared.b16 {%0,%1,%2,%3}, [%4];\n"        \
                 : "=r"(R0), "=r"(R1), "=r"(R2), "=r"(R3) : "r"(ADDR))

#define LDS64(R0, R1, ADDR)                                                               \
    asm volatile("ld.shared.v2.u32 {%0,%1}, [%2];" : "=r"(R0), "=r"(R1) : "r"(ADDR))

#define CP_ASYNC16(DST, SRC)                                                              \
    asm volatile("cp.async.cg.shared.global [%0], [%1], 16;\n" :: "r"(DST), "l"(SRC))
#define CP_COMMIT  asm volatile("cp.async.commit_group;\n")
#define CP_WAIT(N) asm volatile("cp.async.wait_group %0;\n" :: "n"(N))

// ---------------- prep kernels (launch order: init, prep_all, gx, lstm(4th), fc) ----------------
__global__ void init_kernel() {
    int idx = blockIdx.x * blockDim.x + threadIdx.x;
    uint4 z = make_uint4(0u, 0u, 0u, 0u);
    for (int i = idx; i < 32768; i += gridDim.x * blockDim.x)
        reinterpret_cast<uint4*>(g_h)[i] = z;
    if (idx < NCTA * 4) g_flag[idx] = 0;
}

__global__ void prep_all_kernel(const float* __restrict__ x,
                                const float* __restrict__ Wih, const float* __restrict__ Whh,
                                const float* __restrict__ bih, const float* __restrict__ bhh,
                                const float* __restrict__ Wfc) {
    size_t idx = (size_t)blockIdx.x * blockDim.x + threadIdx.x;
    if (idx < (size_t)4096 * HID)
        g_Wc[idx] = __float2bfloat16(Whh[idx]);
    if (idx < (size_t)4096 * 96) {
        int n = (int)(idx / 96), k = (int)(idx % 96);
        float v = (k < FEAT) ? Wih[(size_t)n * FEAT + k] : 0.f;
        g_Wxb[idx] = __float2bfloat16(v);
    }
    if (idx < 4096) g_bsum[idx] = bih[idx] + bhh[idx];
    if (idx < (size_t)CLS * HID) g_Wfcb[idx] = __float2bfloat16(Wfc[idx]);
    if (idx < (size_t)T_STEPS * BATCH * FEAT)
        g_xb[idx] = __float2bfloat16(x[idx]);
}

// gx = x @ Wih^T + bsum, bf16. grid = 2048 row-tiles (64 rows), 256 threads.
// Per block: A (64x96) staged once; loops 16 col-tiles of 256.
__global__ void __launch_bounds__(256)
gx_kernel()
{
    extern __shared__ char gs[];
    __nv_bfloat16* Ax = reinterpret_cast<__nv_bfloat16*>(gs);            // 64 x 104
    __nv_bfloat16* Bw = Ax + 64 * 104;                                   // 256 x 104

    const int tid  = threadIdx.x;
    const int lane = tid & 31, wid = tid >> 5;
    const int r0   = blockIdx.x * 64;
    const int rowt = (wid & 3) * 16;
    const int colg = (wid >> 2) * 128;

    const unsigned ax_u = smem_u32(Ax);
    const unsigned bw_u = smem_u32(Bw);

    // zero A pad cols 88..95
    for (int i = tid; i < 64 * 4; i += 256)
        reinterpret_cast<unsigned*>(Ax)[(i >> 2) * 52 + 44 + (i & 3)] = 0u;
    // stage A: 64 rows x 11 segs of 16B
    for (int i = tid; i < 64 * 11; i += 256) {
        int row = i / 11, seg = i % 11;
        unsigned dst = ax_u + (unsigned)((row * 104 + seg * 8) * 2);
        CP_ASYNC16(dst, g_xb + (size_t)(r0 + row) * FEAT + seg * 8);
    }
    CP_COMMIT;

    for (int ci = 0; ci < 16; ++ci) {
        const int c0 = ci * 256;
        // stage B: 256 rows x 12 segs
        for (int i = tid; i < 256 * 12; i += 256) {
            int row = i / 12, seg = i % 12;
            unsigned dst = bw_u + (unsigned)((row * 104 + seg * 8) * 2);
            CP_ASYNC16(dst, g_Wxb + (size_t)(c0 + row) * 96 + seg * 8);
        }
        CP_COMMIT;
        CP_WAIT(0);
        __syncthreads();

        float acc[16][4];
#pragma unroll
        for (int i = 0; i < 16; ++i)
#pragma unroll
            for (int j = 0; j < 4; ++j) acc[i][j] = 0.f;

#pragma unroll
        for (int ks = 0; ks < 6; ++ks) {
            int kk = ks * 16;
            unsigned a0, a1, a2, a3;
            unsigned addr = ax_u +
                (unsigned)(((rowt + (lane & 15)) * 104 + kk + ((lane >> 4) << 3)) * 2);
            LDMATRIX_X4(a0, a1, a2, a3, addr);
#pragma unroll
            for (int nf = 0; nf < 16; ++nf) {
                int n = colg + nf * 8 + (lane >> 2);
                unsigned baddr = bw_u + (unsigned)((n * 104 + kk + ((lane & 3) << 1)) * 2);
                unsigned b0r, b1r;
                asm volatile("ld.shared.b32 %0, [%1];" : "=r"(b0r) : "r"(baddr));
                asm volatile("ld.shared.b32 %0, [%1];" : "=r"(b1r) : "r"(baddr + 16));
                MMA_BF16(acc[nf], a0, a1, a2, a3, b0r, b1r);
            }
        }
        __syncthreads();

        // epilogue: + bias, bf16x2 store
#pragma unroll
        for (int half = 0; half < 2; ++half) {
            int r = rowt + (lane >> 2) + half * 8;
            size_t rbase = (size_t)(r0 + r) * 4096;
#pragma unroll
            for (int nf = 0; nf < 16; ++nf) {
                int c = c0 + colg + nf * 8 + ((lane & 3) << 1);
                float v0 = acc[nf][half * 2 + 0] + __ldg(g_bsum + c);
                float v1 = acc[nf][half * 2 + 1] + __ldg(g_bsum + c + 1);
                __nv_bfloat162 b2 = __floats2bfloat162_rn(v0, v1);
                *reinterpret_cast<unsigned*>(&g_gx[rbase + c]) =
                    *reinterpret_cast<unsigned*>(&b2);
            }
        }
    }
}

// ---------------- persistent LSTM kernel (R7 chassis; K=1024; tile-skip; early exit) ----------------
__global__ void __launch_bounds__(NTHR, 1)
lstm_kernel(const int* __restrict__ lens)
{
    extern __shared__ char smem_raw[];
    __nv_bfloat16* Ws  = reinterpret_cast<__nv_bfloat16*>(smem_raw);        // 64 * WS_STRIDE
    __nv_bfloat16* As  = Ws + 64 * WS_STRIDE;                               // NBUF * 64 * ASTR
    float* gsm         = reinterpret_cast<float*>(As + 64 * ASTR);          // aliases ring buf 1
    __nv_bfloat16* Gb  = As + NBUF * 64 * ASTR;                             // 64 * GBSTR
    int*   len_s       = reinterpret_cast<int*>(Gb + 64 * GBSTR);           // 64

    const int tid   = threadIdx.x;
    const int bid   = blockIdx.x;
    const int cta_m = bid & 1;
    const int cta_n = bid >> 1;
    const int b0    = cta_m * MT;
    const int hid0  = cta_n * UPC;

    // resident W_hh slice, k-permuted per 16-half group (pair q <- (q>>1)+((q&1)<<2))
    for (int i = tid; i < 64 * (HID / 2); i += NTHR) {
        int n = i / (HID / 2), j = i % (HID / 2);
        int g16 = j >> 3, q = j & 7;
        int sp  = (q >> 1) + ((q & 1) << 2);
        int g = n >> 4, u = n & 15;
        const unsigned* src = reinterpret_cast<const unsigned*>(
                g_Wc + (size_t)(g * HID + hid0 + u) * HID);
        reinterpret_cast<unsigned*>(Ws + (size_t)n * WS_STRIDE)[j] = src[g16 * 8 + sp];
    }
    if (tid < 64) len_s[tid] = lens[b0 + tid];
    __syncthreads();

    const int lane = tid & 31, wid = tid >> 5;
    const int wm = wid & 1;        // 0..1 : 32 rows
    const int wn = wid >> 1;       // 0..3 : 16 cols
    const int eu  = tid & 15;
    const int eb0 = tid >> 4;

    const unsigned ws_u = smem_u32(Ws);
    const unsigned as_u = smem_u32(As);
    const unsigned gb_u = smem_u32(Gb);

    const bool watcher = (tid < 64);
    int* const my_fp   = &g_flag[(((tid & 63) << 1) | cta_m) << 2];

    const int len0 = len_s[0];                 // max length in this half (sorted desc)
    const int lt0  = len_s[wm * 32];           // M-tile mi=0 active bound
    const int lt1  = len_s[wm * 32 + 16];      // M-tile mi=1 active bound

    float hreg[4] = {0.f, 0.f, 0.f, 0.f};
    float creg[4] = {0.f, 0.f, 0.f, 0.f};

    for (int t = 0; t < T_STEPS; ++t) {
        const __nv_bfloat16* __restrict__ h_cur = g_h[t & 1];
        __nv_bfloat16* __restrict__ h_nxt = g_h[(t & 1) ^ 1];

        // whole-CTA early exit: all rows frozen
        if (t >= len0) {
#pragma unroll
            for (int p = 0; p < 4; ++p) {
                int bl = eb0 + p * 16;
                h_nxt[(b0 + bl) * HID + hid0 + eu] = __float2bfloat16(hreg[p]);
            }
            __threadfence();
            __syncthreads();
            if (tid == 0)
                asm volatile("st.release.gpu.global.b32 [%0], %1;"
                             :: "l"(&g_flag[bid << 2]), "r"(T_STEPS) : "memory");
            CP_WAIT(0);
            break;
        }

        // stage gx slice for step t (h-independent): 64 rows x 4 gates x 2 segs
        {
#pragma unroll
            for (int r = 0; r < 2; ++r) {
                int slot = tid + r * NTHR;          // 0..511 = 64 rows x 8 segs
                int row = slot >> 3, seg = slot & 7;
                int g = seg >> 1, half8 = seg & 1;
                unsigned dst = gb_u + (unsigned)((row * GBSTR + g * 16 + half8 * 8) * 2);
                CP_ASYNC16(dst, g_gx + ((size_t)t * BATCH + b0 + row) * 4096 +
                                g * HID + hid0 + half8 * 8);
            }
            CP_COMMIT;
        }

        // half-barrier: 64 same-half CTAs have published step t-1
        if (t > 0) {
            int fv = 0x7fffffff;
            if (watcher)
                asm volatile("ld.acquire.gpu.global.b32 %0, [%1];" : "=r"(fv) : "l"(my_fp) : "memory");
            for (;;) {
                if (__syncthreads_count(fv >= t) == NTHR) break;
                if (watcher && fv < t)
                    asm volatile("ld.acquire.gpu.global.b32 %0, [%1];" : "=r"(fv) : "l"(my_fp) : "memory");
            }
        }

        // stage h chunk s (1..8) into ring buf s&3
        auto stage = [&](int s) {
            unsigned dstb = as_u + (unsigned)((s & 3) * 64 * ASTR * 2);
#pragma unroll
            for (int r = 0; r < 4; ++r) {
                int slot = tid + r * NTHR;          // 1024 slots = 64 rows x 16 seg
                int row = slot >> 4, c16 = slot & 15;
                unsigned dst = dstb + (unsigned)((row * ASTR + c16 * 8) * 2);
                CP_ASYNC16(dst, h_cur + (size_t)(b0 + row) * HID + (s - 1) * CW + c16 * 8);
            }
            CP_COMMIT;
        };

        stage(1);
        stage(2);
        stage(3);

        float acc[2][2][4];
#pragma unroll
        for (int a = 0; a < 2; ++a)
#pragma unroll
            for (int b = 0; b < 2; ++b)
#pragma unroll
                for (int c = 0; c < 4; ++c) acc[a][b][c] = 0.f;

#pragma unroll
        for (int s = 1; s <= 8; ++s) {
            if (s <= 6)      { CP_WAIT(2); }
            else if (s == 7) { CP_WAIT(1); }
            else             { CP_WAIT(0); }
            __syncthreads();
            if (s + 3 <= 8) stage(s + 3);

            const int kcol = (s - 1) * CW;
            const unsigned abase = as_u + (unsigned)((s & 3) * 64 * ASTR * 2);
            if (t < lt0) {
#pragma unroll
                for (int ks = 0; ks < 8; ++ks) {
                    const int kk = ks * 16;
                    const int kg = kcol + kk;
                    unsigned a0r[4];
                    unsigned addr0 = abase +
                        (unsigned)(((wm * 32 + (lane & 15)) * ASTR + kk + ((lane >> 4) << 3)) * 2);
                    LDMATRIX_X4(a0r[0], a0r[1], a0r[2], a0r[3], addr0);
                    unsigned bfr[2][2];
#pragma unroll
                    for (int nf = 0; nf < 2; ++nf) {
                        int n = wn * 16 + nf * 8 + (lane >> 2);
                        unsigned baddr = ws_u +
                            (unsigned)((n * WS_STRIDE + kg) * 2) + ((lane & 3) << 3);
                        LDS64(bfr[nf][0], bfr[nf][1], baddr);
                        MMA_BF16(acc[0][nf], a0r[0], a0r[1], a0r[2], a0r[3], bfr[nf][0], bfr[nf][1]);
                    }
                    if (t < lt1) {
                        unsigned a1r[4];
                        unsigned addr1 = abase +
                            (unsigned)(((wm * 32 + 16 + (lane & 15)) * ASTR + kk + ((lane >> 4) << 3)) * 2);
                        LDMATRIX_X4(a1r[0], a1r[1], a1r[2], a1r[3], addr1);
#pragma unroll
                        for (int nf = 0; nf < 2; ++nf)
                            MMA_BF16(acc[1][nf], a1r[0], a1r[1], a1r[2], a1r[3], bfr[nf][0], bfr[nf][1]);
                    }
                }
            }
        }
        __syncthreads();

        // accumulators -> gsm (aliases ring buf 1; all computes done)
#pragma unroll
        for (int mi = 0; mi < 2; ++mi) {
            int r = wm * 32 + mi * 16 + (lane >> 2);
#pragma unroll
            for (int nf = 0; nf < 2; ++nf) {
                int c = wn * 16 + nf * 8 + ((lane & 3) << 1);
                gsm[r * GSM_STRIDE + c]           = acc[mi][nf][0];
                gsm[r * GSM_STRIDE + c + 1]       = acc[mi][nf][1];
                gsm[(r + 8) * GSM_STRIDE + c]     = acc[mi][nf][2];
                gsm[(r + 8) * GSM_STRIDE + c + 1] = acc[mi][nf][3];
            }
        }
        __syncthreads();

        // LSTM cell: thread owns (b_local = eb0 + 16p, unit = eu); gate base from Gb
#pragma unroll
        for (int p = 0; p < 4; ++p) {
            int bl = eb0 + p * 16;
            float gb0 = __bfloat162float(Gb[bl * GBSTR + eu]);
            float gb1 = __bfloat162float(Gb[bl * GBSTR + 16 + eu]);
            float gb2 = __bfloat162float(Gb[bl * GBSTR + 32 + eu]);
            float gb3 = __bfloat162float(Gb[bl * GBSTR + 48 + eu]);
            float gi = gsm[bl * GSM_STRIDE + eu]        + gb0;
            float gf = gsm[bl * GSM_STRIDE + 16 + eu]   + gb1;
            float gg = gsm[bl * GSM_STRIDE + 32 + eu]   + gb2;
            float go = gsm[bl * GSM_STRIDE + 48 + eu]   + gb3;
            float ii = sigmoidf_(gi);
            float ff = sigmoidf_(gf);
            float gt = tanhf_(gg);
            float oo = sigmoidf_(go);
            float cn = ff * creg[p] + ii * gt;
            float hn = oo * tanhf_(cn);
            bool  m  = t < len_s[bl];
            float h2 = m ? hn : hreg[p];
            creg[p]  = m ? cn : creg[p];
            hreg[p]  = h2;
            h_nxt[(b0 + bl) * HID + hid0 + eu] = __float2bfloat16(h2);
        }

        // publish step t
        __threadfence();
        __syncthreads();
        if (tid == 0)
            asm volatile("st.release.gpu.global.b32 [%0], %1;"
                         :: "l"(&g_flag[bid << 2]), "r"(t + 1) : "memory");

        // g_Hall: no inter-CTA consumer -> off critical path
#pragma unroll
        for (int p = 0; p < 4; ++p) {
            int bl = eb0 + p * 16;
            g_Hall[((size_t)t * BATCH + b0 + bl) * HID + hid0 + eu] =
                __float2bfloat16(hreg[p]);
        }
    }
}

// ---------------- FC head: logits + binary expansion ----------------
__global__ void __launch_bounds__(128)
fc_kernel(const int* __restrict__ lens, const float* __restrict__ bfc,
          float* __restrict__ out)
{
    __shared__ __nv_bfloat16 As[64 * FC_ASTR];
    __shared__ __nv_bfloat16 Bs[88 * FC_ASTR];

    const int tid  = threadIdx.x;
    const int lane = tid & 31, wid = tid >> 5;
    const int r0   = blockIdx.x * 64;

    float acc[11][4];
#pragma unroll
    for (int i = 0; i < 11; ++i)
#pragma unroll
        for (int j = 0; j < 4; ++j) acc[i][j] = 0.f;

    const unsigned as_u = smem_u32(As);
    const unsigned bs_u = smem_u32(Bs);

    for (int ch = 0; ch < 16; ++ch) {
        __syncthreads();
        const int k0 = ch * 64;
        for (int i = tid; i < 512; i += 128) {
            int row = i >> 3, c8 = i & 7;
            uint4 v = *(reinterpret_cast<const uint4*>(
                    g_Hall + (size_t)(r0 + row) * HID + k0) + c8);
            *(reinterpret_cast<uint4*>(As + row * FC_ASTR) + c8) = v;
        }
        for (int i = tid; i < 704; i += 128) {
            int row = i >> 3, c8 = i & 7;
            uint4 v = *(reinterpret_cast<const uint4*>(
                    g_Wfcb + (size_t)row * HID + k0) + c8);
            *(reinterpret_cast<uint4*>(Bs + row * FC_ASTR) + c8) = v;
        }
        __syncthreads();
#pragma unroll
        for (int ks = 0; ks < 4; ++ks) {
            int kk = ks * 16;
            unsigned a0, a1, a2, a3;
            unsigned addr = as_u +
                (unsigned)(((wid * 16 + (lane & 15)) * FC_ASTR + kk + ((lane >> 4) << 3)) * 2);
            LDMATRIX_X4(a0, a1, a2, a3, addr);
#pragma unroll
            for (int nf = 0; nf < 11; ++nf) {
                int n = nf * 8 + (lane >> 2);
                unsigned baddr = bs_u +
                    (unsigned)((n * FC_ASTR + kk + ((lane & 3) << 1)) * 2);
                unsigned b0r, b1r;
                asm volatile("ld.shared.b32 %0, [%1];" : "=r"(b0r) : "r"(baddr));
                asm volatile("ld.shared.b32 %0, [%1];" : "=r"(b1r) : "r"(baddr + 16));
                MMA_BF16(acc[nf], a0, a1, a2, a3, b0r, b1r);
            }
        }
    }

#pragma unroll
    for (int half = 0; half < 2; ++half) {
        int r  = wid * 16 + (lane >> 2) + half * 8;
        int tb = r0 + r;
        int t  = tb >> 7;
        int b  = tb & 127;
        bool m = t < __ldg(lens + b);
        size_t obase = ((size_t)b * T_STEPS + t) * CLS * 2;
#pragma unroll
        for (int nf = 0; nf < 11; ++nf) {
            int c = nf * 8 + ((lane & 3) << 1);
            float l0 = acc[nf][half * 2 + 0] + __ldg(bfc + c);
            float l1 = acc[nf][half * 2 + 1] + __ldg(bfc + c + 1);
            if (!m) { l0 = 0.f; l1 = 0.f; }
            float4 v = make_float4(l0, 1.f - l0, l1, 1.f - l1);
            *reinterpret_cast<float4*>(out + obase + (size_t)c * 2) = v;
        }
    }
}

// ---------------- launch ----------------
extern "C" void kernel_launch(void* const* d_in, const int* in_sizes, int n_in,
                              void* d_out, int out_size) {
    const float* x    = (const float*)d_in[0];
    const int*   lens = (const int*)d_in[1];    // int32 (JAX x64 disabled)
    const float* Wih  = (const float*)d_in[2];
    const float* Whh  = (const float*)d_in[3];
    const float* bih  = (const float*)d_in[4];
    const float* bhh  = (const float*)d_in[5];
    const float* Wfc  = (const float*)d_in[6];
    const float* bfc  = (const float*)d_in[7];
    float*       out  = (float*)d_out;
    (void)in_sizes; (void)n_in; (void)out_size;

    // launch order: init(1), prep_all(2), gx(3), lstm(4 = ncu slot), fc(5)
    init_kernel<<<64, 256>>>();
    {
        size_t tot = (size_t)T_STEPS * BATCH * FEAT;   // largest range covered
        prep_all_kernel<<<(unsigned)((tot + 255) / 256), 256>>>(x, Wih, Whh, bih, bhh, Wfc);
    }
    {
        int gx_smem = (64 * 104 + 256 * 104) * 2;      // 66,560 B
        cudaFuncSetAttribute(gx_kernel, cudaFuncAttributeMaxDynamicSharedMemorySize, gx_smem);
        gx_kernel<<<(T_STEPS * BATCH) / 64, 256, gx_smem>>>();
    }

    int smem = 64 * WS_STRIDE * 2          // resident W slice   (132,096)
             + NBUF * 64 * ASTR * 2        // A-stage ring       (69,632; buf1 doubles as gsm)
             + 64 * GBSTR * 2              // gx slice           (9,216)
             + 64 * 4;                     // lengths
    cudaFuncSetAttribute(lstm_kernel, cudaFuncAttributeMaxDynamicSharedMemorySize, smem);
    lstm_kernel<<<NCTA, NTHR, smem>>>(lens);

    fc_kernel<<<(T_STEPS * BATCH) / 64, 128>>>(lens, bfc, out);
}

// round 13
// speedup vs baseline: 1.1553x; 1.1193x over previous
#include <cuda_runtime.h>
#include <cuda_bf16.h>
#include <cstdint>

#define T_STEPS 1024
#define BATCH   128
#define FEAT    88
#define HID     1024
#define CLS     88
#define NCTA    128
#define NTHR    256
#define MT      64            // batch rows per CTA
#define UPC     16            // hidden units per CTA -> 64 gate cols
#define CW      128           // h chunk width (K cols)
#define WS_STRIDE 1032        // resident-W row stride (halfs): 4-word/row bank shift
#define ASTR    136           // A-tile row stride (halfs)
#define NBUF    4
#define GBSTR   72            // gx-slice row stride (halfs)
#define GSM_STRIDE 68
#define FC_ASTR 72

// ---------------- device globals ----------------
__device__ __nv_bfloat16 g_Wc[(size_t)4096 * HID];                 // bf16 W_hh
__device__ __nv_bfloat16 g_Wxb[(size_t)4096 * 96];                 // bf16 W_ih padded to 96
__device__ __nv_bfloat16 g_Wfcb[(size_t)CLS * HID];
__device__ float         g_bsum[4096];
__device__ __nv_bfloat16 g_xb[(size_t)T_STEPS * BATCH * FEAT];
__device__ __nv_bfloat16 g_gx[(size_t)T_STEPS * BATCH * 4096];     // precomputed x@Wih^T + bias
__device__ __nv_bfloat16 g_h[2][BATCH * HID];
__device__ __nv_bfloat16 g_Hall[(size_t)T_STEPS * BATCH * HID];
__device__ int           g_flag[NCTA * 4];

// ---------------- helpers ----------------
__device__ __forceinline__ unsigned smem_u32(const void* p) {
    return (unsigned)__cvta_generic_to_shared(p);
}
__device__ __forceinline__ float sigmoidf_(float x) {
    return 1.0f / (1.0f + __expf(-x));
}
__device__ __forceinline__ float tanhf_(float x) {
    float ax = fabsf(x);
    float e  = __expf(-2.0f * ax);
    float r  = (1.0f - e) / (1.0f + e);
    return (x < 0.0f) ? -r : r;
}

#define MMA_BF16(ACC, A0, A1, A2, A3, B0, B1)                                             \
    asm volatile(                                                                         \
        "mma.sync.aligned.m16n8k16.row.col.f32.bf16.bf16.f32 "                            \
        "{%0,%1,%2,%3}, {%4,%5,%6,%7}, {%8,%9}, {%0,%1,%2,%3};\n"                         \
        : "+f"((ACC)[0]), "+f"((ACC)[1]), "+f"((ACC)[2]), "+f"((ACC)[3])                  \
        : "r"(A0), "r"(A1), "r"(A2), "r"(A3), "r"(B0), "r"(B1))

#define LDMATRIX_X4(R0, R1, R2, R3, ADDR)                                                 \
    asm volatile("ldmatrix.sync.aligned.m8n8.x4.shared.b16 {%0,%1,%2,%3}, [%4];\n"        \
                 : "=r"(R0), "=r"(R1), "=r"(R2), "=r"(R3) : "r"(ADDR))

#define LDS64(R0, R1, ADDR)                                                               \
    asm volatile("ld.shared.v2.u32 {%0,%1}, [%2];" : "=r"(R0), "=r"(R1) : "r"(ADDR))

#define CP_ASYNC16(DST, SRC)                                                              \
    asm volatile("cp.async.cg.shared.global [%0], [%1], 16;\n" :: "r"(DST), "l"(SRC))
#define CP_COMMIT  asm volatile("cp.async.commit_group;\n")
#define CP_WAIT(N) asm volatile("cp.async.wait_group %0;\n" :: "n"(N))

// ---------------- prep kernels (launch order: init, prep_all, gx, lstm(4th), fc) ----------------
__global__ void init_kernel() {
    int idx = blockIdx.x * blockDim.x + threadIdx.x;
    uint4 z = make_uint4(0u, 0u, 0u, 0u);
    for (int i = idx; i < 32768; i += gridDim.x * blockDim.x)
        reinterpret_cast<uint4*>(g_h)[i] = z;
    if (idx < NCTA * 4) g_flag[idx] = 0;
}

__global__ void prep_all_kernel(const float* __restrict__ x,
                                const float* __restrict__ Wih, const float* __restrict__ Whh,
                                const float* __restrict__ bih, const float* __restrict__ bhh,
                                const float* __restrict__ Wfc) {
    size_t idx = (size_t)blockIdx.x * blockDim.x + threadIdx.x;
    if (idx < (size_t)4096 * HID)
        g_Wc[idx] = __float2bfloat16(Whh[idx]);
    if (idx < (size_t)4096 * 96) {
        int n = (int)(idx / 96), k = (int)(idx % 96);
        float v = (k < FEAT) ? Wih[(size_t)n * FEAT + k] : 0.f;
        g_Wxb[idx] = __float2bfloat16(v);
    }
    if (idx < 4096) g_bsum[idx] = bih[idx] + bhh[idx];
    if (idx < (size_t)CLS * HID) g_Wfcb[idx] = __float2bfloat16(Wfc[idx]);
    if (idx < (size_t)T_STEPS * BATCH * FEAT)
        g_xb[idx] = __float2bfloat16(x[idx]);
}

// gx = x @ Wih^T + bsum, bf16. grid = 2048 row-tiles (64 rows), 256 threads.
__global__ void __launch_bounds__(256)
gx_kernel()
{
    extern __shared__ char gs[];
    __nv_bfloat16* Ax = reinterpret_cast<__nv_bfloat16*>(gs);            // 64 x 104
    __nv_bfloat16* Bw = Ax + 64 * 104;                                   // 256 x 104

    const int tid  = threadIdx.x;
    const int lane = tid & 31, wid = tid >> 5;
    const int r0   = blockIdx.x * 64;
    const int rowt = (wid & 3) * 16;
    const int colg = (wid >> 2) * 128;

    const unsigned ax_u = smem_u32(Ax);
    const unsigned bw_u = smem_u32(Bw);

    for (int i = tid; i < 64 * 4; i += 256)
        reinterpret_cast<unsigned*>(Ax)[(i >> 2) * 52 + 44 + (i & 3)] = 0u;
    for (int i = tid; i < 64 * 11; i += 256) {
        int row = i / 11, seg = i % 11;
        unsigned dst = ax_u + (unsigned)((row * 104 + seg * 8) * 2);
        CP_ASYNC16(dst, g_xb + (size_t)(r0 + row) * FEAT + seg * 8);
    }
    CP_COMMIT;

    for (int ci = 0; ci < 16; ++ci) {
        const int c0 = ci * 256;
        for (int i = tid; i < 256 * 12; i += 256) {
            int row = i / 12, seg = i % 12;
            unsigned dst = bw_u + (unsigned)((row * 104 + seg * 8) * 2);
            CP_ASYNC16(dst, g_Wxb + (size_t)(c0 + row) * 96 + seg * 8);
        }
        CP_COMMIT;
        CP_WAIT(0);
        __syncthreads();

        float acc[16][4];
#pragma unroll
        for (int i = 0; i < 16; ++i)
#pragma unroll
            for (int j = 0; j < 4; ++j) acc[i][j] = 0.f;

#pragma unroll
        for (int ks = 0; ks < 6; ++ks) {
            int kk = ks * 16;
            unsigned a0, a1, a2, a3;
            unsigned addr = ax_u +
                (unsigned)(((rowt + (lane & 15)) * 104 + kk + ((lane >> 4) << 3)) * 2);
            LDMATRIX_X4(a0, a1, a2, a3, addr);
#pragma unroll
            for (int nf = 0; nf < 16; ++nf) {
                int n = colg + nf * 8 + (lane >> 2);
                unsigned baddr = bw_u + (unsigned)((n * 104 + kk + ((lane & 3) << 1)) * 2);
                unsigned b0r, b1r;
                asm volatile("ld.shared.b32 %0, [%1];" : "=r"(b0r) : "r"(baddr));
                asm volatile("ld.shared.b32 %0, [%1];" : "=r"(b1r) : "r"(baddr + 16));
                MMA_BF16(acc[nf], a0, a1, a2, a3, b0r, b1r);
            }
        }
        __syncthreads();

#pragma unroll
        for (int half = 0; half < 2; ++half) {
            int r = rowt + (lane >> 2) + half * 8;
            size_t rbase = (size_t)(r0 + r) * 4096;
#pragma unroll
            for (int nf = 0; nf < 16; ++nf) {
                int c = c0 + colg + nf * 8 + ((lane & 3) << 1);
                float v0 = acc[nf][half * 2 + 0] + __ldg(g_bsum + c);
                float v1 = acc[nf][half * 2 + 1] + __ldg(g_bsum + c + 1);
                __nv_bfloat162 b2 = __floats2bfloat162_rn(v0, v1);
                *reinterpret_cast<unsigned*>(&g_gx[rbase + c]) =
                    *reinterpret_cast<unsigned*>(&b2);
            }
        }
    }
}

// ---------------- persistent LSTM kernel ----------------
// R7 chassis; K=1024 (gx hoisted); tile-skip with CHUNK-LEVEL path selection
// (no per-ks branches); whole-half early exit; single-thread-fence publish.
__global__ void __launch_bounds__(NTHR, 1)
lstm_kernel(const int* __restrict__ lens)
{
    extern __shared__ char smem_raw[];
    __nv_bfloat16* Ws  = reinterpret_cast<__nv_bfloat16*>(smem_raw);        // 64 * WS_STRIDE
    __nv_bfloat16* As  = Ws + 64 * WS_STRIDE;                               // NBUF * 64 * ASTR
    float* gsm         = reinterpret_cast<float*>(As + 64 * ASTR);          // aliases ring buf 1
    __nv_bfloat16* Gb  = As + NBUF * 64 * ASTR;                             // 64 * GBSTR
    int*   len_s       = reinterpret_cast<int*>(Gb + 64 * GBSTR);           // 64

    const int tid   = threadIdx.x;
    const int bid   = blockIdx.x;
    const int cta_m = bid & 1;
    const int cta_n = bid >> 1;
    const int b0    = cta_m * MT;
    const int hid0  = cta_n * UPC;

    // resident W_hh slice, k-permuted per 16-half group (pair q <- (q>>1)+((q&1)<<2))
    for (int i = tid; i < 64 * (HID / 2); i += NTHR) {
        int n = i / (HID / 2), j = i % (HID / 2);
        int g16 = j >> 3, q = j & 7;
        int sp  = (q >> 1) + ((q & 1) << 2);
        int g = n >> 4, u = n & 15;
        const unsigned* src = reinterpret_cast<const unsigned*>(
                g_Wc + (size_t)(g * HID + hid0 + u) * HID);
        reinterpret_cast<unsigned*>(Ws + (size_t)n * WS_STRIDE)[j] = src[g16 * 8 + sp];
    }
    if (tid < 64) len_s[tid] = lens[b0 + tid];
    __syncthreads();

    const int lane = tid & 31, wid = tid >> 5;
    const int wm = wid & 1;        // 0..1 : 32 rows
    const int wn = wid >> 1;       // 0..3 : 16 cols
    const int eu  = tid & 15;
    const int eb0 = tid >> 4;

    const unsigned ws_u = smem_u32(Ws);
    const unsigned as_u = smem_u32(As);
    const unsigned gb_u = smem_u32(Gb);

    const bool watcher = (tid < 64);
    int* const my_fp   = &g_flag[(((tid & 63) << 1) | cta_m) << 2];

    const int len0 = len_s[0];                 // max length in this half
    const int lt0  = len_s[wm * 32];           // M-tile mi=0 bound (this warp)
    const int lt1  = len_s[wm * 32 + 16];      // M-tile mi=1 bound

    float hreg[4] = {0.f, 0.f, 0.f, 0.f};
    float creg[4] = {0.f, 0.f, 0.f, 0.f};

    for (int t = 0; t < T_STEPS; ++t) {
        const __nv_bfloat16* __restrict__ h_cur = g_h[t & 1];
        __nv_bfloat16* __restrict__ h_nxt = g_h[(t & 1) ^ 1];

        // whole-CTA early exit: all rows of this half frozen
        if (t >= len0) {
#pragma unroll
            for (int p = 0; p < 4; ++p) {
                int bl = eb0 + p * 16;
                h_nxt[(b0 + bl) * HID + hid0 + eu] = __float2bfloat16(hreg[p]);
            }
            __syncthreads();
            if (tid == 0) {
                asm volatile("membar.gl;" ::: "memory");
                __stcg(&g_flag[bid << 2], T_STEPS);
            }
            CP_WAIT(0);
            break;
        }

        // stage gx slice for step t (h-independent, pre-barrier)
        {
#pragma unroll
            for (int r = 0; r < 2; ++r) {
                int slot = tid + r * NTHR;          // 0..511 = 64 rows x 8 segs
                int row = slot >> 3, seg = slot & 7;
                int g = seg >> 1, half8 = seg & 1;
                unsigned dst = gb_u + (unsigned)((row * GBSTR + g * 16 + half8 * 8) * 2);
                CP_ASYNC16(dst, g_gx + ((size_t)t * BATCH + b0 + row) * 4096 +
                                g * HID + hid0 + half8 * 8);
            }
            CP_COMMIT;
        }

        // half-barrier: 64 same-half CTAs have published step t-1
        if (t > 0) {
            int fv = 0x7fffffff;
            if (watcher)
                asm volatile("ld.acquire.gpu.global.b32 %0, [%1];" : "=r"(fv) : "l"(my_fp) : "memory");
            for (;;) {
                if (__syncthreads_count(fv >= t) == NTHR) break;
                if (watcher && fv < t)
                    asm volatile("ld.acquire.gpu.global.b32 %0, [%1];" : "=r"(fv) : "l"(my_fp) : "memory");
            }
        }

        auto stage = [&](int s) {
            unsigned dstb = as_u + (unsigned)((s & 3) * 64 * ASTR * 2);
#pragma unroll
            for (int r = 0; r < 4; ++r) {
                int slot = tid + r * NTHR;          // 1024 slots = 64 rows x 16 seg
                int row = slot >> 4, c16 = slot & 15;
                unsigned dst = dstb + (unsigned)((row * ASTR + c16 * 8) * 2);
                CP_ASYNC16(dst, h_cur + (size_t)(b0 + row) * HID + (s - 1) * CW + c16 * 8);
            }
            CP_COMMIT;
        };

        stage(1);
        stage(2);
        stage(3);

        float acc[2][2][4];
#pragma unroll
        for (int a = 0; a < 2; ++a)
#pragma unroll
            for (int b = 0; b < 2; ++b)
#pragma unroll
                for (int c = 0; c < 4; ++c) acc[a][b][c] = 0.f;

        const bool act1 = (t < lt1);        // both tiles active (warp-uniform)
        const bool act0 = (t < lt0);        // tile 0 active

#pragma unroll
        for (int s = 1; s <= 8; ++s) {
            if (s <= 6)      { CP_WAIT(2); }
            else if (s == 7) { CP_WAIT(1); }
            else             { CP_WAIT(0); }
            __syncthreads();
            if (s + 3 <= 8) stage(s + 3);

            const int kcol = (s - 1) * CW;
            const unsigned abase = as_u + (unsigned)((s & 3) * 64 * ASTR * 2);

            if (act1) {
                // both M-tiles: straight-line, no inner branches
#pragma unroll
                for (int ks = 0; ks < 8; ++ks) {
                    const int kk = ks * 16;
                    const int kg = kcol + kk;
                    unsigned a0r[4], a1r[4], bfr[2][2];
                    unsigned addr0 = abase +
                        (unsigned)(((wm * 32 + (lane & 15)) * ASTR + kk + ((lane >> 4) << 3)) * 2);
                    LDMATRIX_X4(a0r[0], a0r[1], a0r[2], a0r[3], addr0);
                    LDMATRIX_X4(a1r[0], a1r[1], a1r[2], a1r[3], addr0 + (unsigned)(16 * ASTR * 2));
#pragma unroll
                    for (int nf = 0; nf < 2; ++nf) {
                        int n = wn * 16 + nf * 8 + (lane >> 2);
                        unsigned baddr = ws_u +
                            (unsigned)((n * WS_STRIDE + kg) * 2) + ((lane & 3) << 3);
                        LDS64(bfr[nf][0], bfr[nf][1], baddr);
                        MMA_BF16(acc[0][nf], a0r[0], a0r[1], a0r[2], a0r[3], bfr[nf][0], bfr[nf][1]);
                        MMA_BF16(acc[1][nf], a1r[0], a1r[1], a1r[2], a1r[3], bfr[nf][0], bfr[nf][1]);
                    }
                }
            } else if (act0) {
                // tile 0 only
#pragma unroll
                for (int ks = 0; ks < 8; ++ks) {
                    const int kk = ks * 16;
                    const int kg = kcol + kk;
                    unsigned a0r[4], bfr[2][2];
                    unsigned addr0 = abase +
                        (unsigned)(((wm * 32 + (lane & 15)) * ASTR + kk + ((lane >> 4) << 3)) * 2);
                    LDMATRIX_X4(a0r[0], a0r[1], a0r[2], a0r[3], addr0);
#pragma unroll
                    for (int nf = 0; nf < 2; ++nf) {
                        int n = wn * 16 + nf * 8 + (lane >> 2);
                        unsigned baddr = ws_u +
                            (unsigned)((n * WS_STRIDE + kg) * 2) + ((lane & 3) << 3);
                        LDS64(bfr[nf][0], bfr[nf][1], baddr);
                        MMA_BF16(acc[0][nf], a0r[0], a0r[1], a0r[2], a0r[3], bfr[nf][0], bfr[nf][1]);
                    }
                }
            }
        }
        __syncthreads();

        // accumulators -> gsm (aliases ring buf 1)
#pragma unroll
        for (int mi = 0; mi < 2; ++mi) {
            int r = wm * 32 + mi * 16 + (lane >> 2);
#pragma unroll
            for (int nf = 0; nf < 2; ++nf) {
                int c = wn * 16 + nf * 8 + ((lane & 3) << 1);
                gsm[r * GSM_STRIDE + c]           = acc[mi][nf][0];
                gsm[r * GSM_STRIDE + c + 1]       = acc[mi][nf][1];
                gsm[(r + 8) * GSM_STRIDE + c]     = acc[mi][nf][2];
                gsm[(r + 8) * GSM_STRIDE + c + 1] = acc[mi][nf][3];
            }
        }
        __syncthreads();

        // LSTM cell: thread owns (b_local = eb0 + 16p, unit = eu)
#pragma unroll
        for (int p = 0; p < 4; ++p) {
            int bl = eb0 + p * 16;
            float gb0 = __bfloat162float(Gb[bl * GBSTR + eu]);
            float gb1 = __bfloat162float(Gb[bl * GBSTR + 16 + eu]);
            float gb2 = __bfloat162float(Gb[bl * GBSTR + 32 + eu]);
            float gb3 = __bfloat162float(Gb[bl * GBSTR + 48 + eu]);
            float gi = gsm[bl * GSM_STRIDE + eu]        + gb0;
            float gf = gsm[bl * GSM_STRIDE + 16 + eu]   + gb1;
            float gg = gsm[bl * GSM_STRIDE + 32 + eu]   + gb2;
            float go = gsm[bl * GSM_STRIDE + 48 + eu]   + gb3;
            float ii = sigmoidf_(gi);
            float ff = sigmoidf_(gf);
            float gt = tanhf_(gg);
            float oo = sigmoidf_(go);
            float cn = ff * creg[p] + ii * gt;
            float hn = oo * tanhf_(cn);
            bool  m  = t < len_s[bl];
            float h2 = m ? hn : hreg[p];
            creg[p]  = m ? cn : creg[p];
            hreg[p]  = h2;
            h_nxt[(b0 + bl) * HID + hid0 + eu] = __float2bfloat16(h2);
        }

        // publish step t: barrier, then single-thread gpu fence + flag store
        __syncthreads();
        if (tid == 0) {
            asm volatile("membar.gl;" ::: "memory");
            __stcg(&g_flag[bid << 2], t + 1);
        }

        // g_Hall: no inter-CTA consumer -> off critical path
#pragma unroll
        for (int p = 0; p < 4; ++p) {
            int bl = eb0 + p * 16;
            g_Hall[((size_t)t * BATCH + b0 + bl) * HID + hid0 + eu] =
                __float2bfloat16(hreg[p]);
        }
    }
}

// ---------------- FC head: logits + binary expansion ----------------
__global__ void __launch_bounds__(128)
fc_kernel(const int* __restrict__ lens, const float* __restrict__ bfc,
          float* __restrict__ out)
{
    __shared__ __nv_bfloat16 As[64 * FC_ASTR];
    __shared__ __nv_bfloat16 Bs[88 * FC_ASTR];

    const int tid  = threadIdx.x;
    const int lane = tid & 31, wid = tid >> 5;
    const int r0   = blockIdx.x * 64;

    float acc[11][4];
#pragma unroll
    for (int i = 0; i < 11; ++i)
#pragma unroll
        for (int j = 0; j < 4; ++j) acc[i][j] = 0.f;

    const unsigned as_u = smem_u32(As);
    const unsigned bs_u = smem_u32(Bs);

    for (int ch = 0; ch < 16; ++ch) {
        __syncthreads();
        const int k0 = ch * 64;
        for (int i = tid; i < 512; i += 128) {
            int row = i >> 3, c8 = i & 7;
            uint4 v = *(reinterpret_cast<const uint4*>(
                    g_Hall + (size_t)(r0 + row) * HID + k0) + c8);
            *(reinterpret_cast<uint4*>(As + row * FC_ASTR) + c8) = v;
        }
        for (int i = tid; i < 704; i += 128) {
            int row = i >> 3, c8 = i & 7;
            uint4 v = *(reinterpret_cast<const uint4*>(
                    g_Wfcb + (size_t)row * HID + k0) + c8);
            *(reinterpret_cast<uint4*>(Bs + row * FC_ASTR) + c8) = v;
        }
        __syncthreads();
#pragma unroll
        for (int ks = 0; ks < 4; ++ks) {
            int kk = ks * 16;
            unsigned a0, a1, a2, a3;
            unsigned addr = as_u +
                (unsigned)(((wid * 16 + (lane & 15)) * FC_ASTR + kk + ((lane >> 4) << 3)) * 2);
            LDMATRIX_X4(a0, a1, a2, a3, addr);
#pragma unroll
            for (int nf = 0; nf < 11; ++nf) {
                int n = nf * 8 + (lane >> 2);
                unsigned baddr = bs_u +
                    (unsigned)((n * FC_ASTR + kk + ((lane & 3) << 1)) * 2);
                unsigned b0r, b1r;
                asm volatile("ld.shared.b32 %0, [%1];" : "=r"(b0r) : "r"(baddr));
                asm volatile("ld.shared.b32 %0, [%1];" : "=r"(b1r) : "r"(baddr + 16));
                MMA_BF16(acc[nf], a0, a1, a2, a3, b0r, b1r);
            }
        }
    }

#pragma unroll
    for (int half = 0; half < 2; ++half) {
        int r  = wid * 16 + (lane >> 2) + half * 8;
        int tb = r0 + r;
        int t  = tb >> 7;
        int b  = tb & 127;
        bool m = t < __ldg(lens + b);
        size_t obase = ((size_t)b * T_STEPS + t) * CLS * 2;
#pragma unroll
        for (int nf = 0; nf < 11; ++nf) {
            int c = nf * 8 + ((lane & 3) << 1);
            float l0 = acc[nf][half * 2 + 0] + __ldg(bfc + c);
            float l1 = acc[nf][half * 2 + 1] + __ldg(bfc + c + 1);
            if (!m) { l0 = 0.f; l1 = 0.f; }
            float4 v = make_float4(l0, 1.f - l0, l1, 1.f - l1);
            *reinterpret_cast<float4*>(out + obase + (size_t)c * 2) = v;
        }
    }
}

// ---------------- launch ----------------
extern "C" void kernel_launch(void* const* d_in, const int* in_sizes, int n_in,
                              void* d_out, int out_size) {
    const float* x    = (const float*)d_in[0];
    const int*   lens = (const int*)d_in[1];    // int32 (JAX x64 disabled)
    const float* Wih  = (const float*)d_in[2];
    const float* Whh  = (const float*)d_in[3];
    const float* bih  = (const float*)d_in[4];
    const float* bhh  = (const float*)d_in[5];
    const float* Wfc  = (const float*)d_in[6];
    const float* bfc  = (const float*)d_in[7];
    float*       out  = (float*)d_out;
    (void)in_sizes; (void)n_in; (void)out_size;

    // launch order: init(1), prep_all(2), gx(3), lstm(4 = ncu slot), fc(5)
    init_kernel<<<64, 256>>>();
    {
        size_t tot = (size_t)T_STEPS * BATCH * FEAT;
        prep_all_kernel<<<(unsigned)((tot + 255) / 256), 256>>>(x, Wih, Whh, bih, bhh, Wfc);
    }
    {
        int gx_smem = (64 * 104 + 256 * 104) * 2;      // 66,560 B
        cudaFuncSetAttribute(gx_kernel, cudaFuncAttributeMaxDynamicSharedMemorySize, gx_smem);
        gx_kernel<<<(T_STEPS * BATCH) / 64, 256, gx_smem>>>();
    }

    int smem = 64 * WS_STRIDE * 2          // resident W slice   (132,096)
             + NBUF * 64 * ASTR * 2        // A-stage ring       (69,632; buf1 doubles as gsm)
             + 64 * GBSTR * 2              // gx slice           (9,216)
             + 64 * 4;                     // lengths
    cudaFuncSetAttribute(lstm_kernel, cudaFuncAttributeMaxDynamicSharedMemorySize, smem);
    lstm_kernel<<<NCTA, NTHR, smem>>>(lens);

    fc_kernel<<<(T_STEPS * BATCH) / 64, 128>>>(lens, bfc, out);
}

// round 14
// speedup vs baseline: 1.1813x; 1.0225x over previous
#include <cuda_runtime.h>
#include <cuda_bf16.h>
#include <cstdint>

#define T_STEPS 1024
#define BATCH   128
#define FEAT    88
#define HID     1024
#define CLS     88
#define NCTA    128
#define NTHR    256
#define MT      64            // batch rows per CTA
#define UPC     16            // hidden units per CTA -> 64 gate cols
#define CW      128           // h chunk width (K cols)
#define WS_STRIDE 1032        // resident-W row stride (halfs)
#define ASTR    136           // A-tile row stride (halfs)
#define NBUF    4
#define GBSTR   72            // gx-slice row stride (halfs)
#define FC_ASTR 72

// ---------------- device globals ----------------
__device__ __nv_bfloat16 g_Wc[(size_t)4096 * HID];                 // bf16 W_hh
__device__ __nv_bfloat16 g_Wxb[(size_t)4096 * 96];                 // bf16 W_ih padded to 96
__device__ __nv_bfloat16 g_Wfcb[(size_t)CLS * HID];
__device__ float         g_bsum[4096];
__device__ __nv_bfloat16 g_xb[(size_t)T_STEPS * BATCH * FEAT];
__device__ __nv_bfloat16 g_gx[(size_t)T_STEPS * BATCH * 4096];     // precomputed x@Wih^T + bias
__device__ __nv_bfloat16 g_h[2][BATCH * HID];
__device__ __nv_bfloat16 g_Hall[(size_t)T_STEPS * BATCH * HID];
__device__ int           g_flag[NCTA * 4];

// ---------------- helpers ----------------
__device__ __forceinline__ unsigned smem_u32(const void* p) {
    return (unsigned)__cvta_generic_to_shared(p);
}
__device__ __forceinline__ float sigmoidf_(float x) {
    return 1.0f / (1.0f + __expf(-x));
}
__device__ __forceinline__ float tanhf_(float x) {
    float ax = fabsf(x);
    float e  = __expf(-2.0f * ax);
    float r  = (1.0f - e) / (1.0f + e);
    return (x < 0.0f) ? -r : r;
}

#define MMA_BF16(ACC, A0, A1, A2, A3, B0, B1)                                             \
    asm volatile(                                                                         \
        "mma.sync.aligned.m16n8k16.row.col.f32.bf16.bf16.f32 "                            \
        "{%0,%1,%2,%3}, {%4,%5,%6,%7}, {%8,%9}, {%0,%1,%2,%3};\n"                         \
        : "+f"((ACC)[0]), "+f"((ACC)[1]), "+f"((ACC)[2]), "+f"((ACC)[3])                  \
        : "r"(A0), "r"(A1), "r"(A2), "r"(A3), "r"(B0), "r"(B1))

#define LDMATRIX_X4(R0, R1, R2, R3, ADDR)                                                 \
    asm volatile("ldmatrix.sync.aligned.m8n8.x4.shared.b16 {%0,%1,%2,%3}, [%4];\n"        \
                 : "=r"(R0), "=r"(R1), "=r"(R2), "=r"(R3) : "r"(ADDR))

#define LDS64(R0, R1, ADDR)                                                               \
    asm volatile("ld.shared.v2.u32 {%0,%1}, [%2];" : "=r"(R0), "=r"(R1) : "r"(ADDR))

#define CP_ASYNC16(DST, SRC)                                                              \
    asm volatile("cp.async.cg.shared.global [%0], [%1], 16;\n" :: "r"(DST), "l"(SRC))
#define CP_COMMIT  asm volatile("cp.async.commit_group;\n")
#define CP_WAIT(N) asm volatile("cp.async.wait_group %0;\n" :: "n"(N))

// ---------------- prep kernels (launch order: init, prep_all, gx, lstm(4th), fc) ----------------
__global__ void init_kernel() {
    int idx = blockIdx.x * blockDim.x + threadIdx.x;
    uint4 z = make_uint4(0u, 0u, 0u, 0u);
    for (int i = idx; i < 32768; i += gridDim.x * blockDim.x)
        reinterpret_cast<uint4*>(g_h)[i] = z;
    if (idx < NCTA * 4) g_flag[idx] = 0;
}

__global__ void prep_all_kernel(const float* __restrict__ x,
                                const float* __restrict__ Wih, const float* __restrict__ Whh,
                                const float* __restrict__ bih, const float* __restrict__ bhh,
                                const float* __restrict__ Wfc) {
    size_t idx = (size_t)blockIdx.x * blockDim.x + threadIdx.x;
    if (idx < (size_t)4096 * HID)
        g_Wc[idx] = __float2bfloat16(Whh[idx]);
    if (idx < (size_t)4096 * 96) {
        int n = (int)(idx / 96), k = (int)(idx % 96);
        float v = (k < FEAT) ? Wih[(size_t)n * FEAT + k] : 0.f;
        g_Wxb[idx] = __float2bfloat16(v);
    }
    if (idx < 4096) g_bsum[idx] = bih[idx] + bhh[idx];
    if (idx < (size_t)CLS * HID) g_Wfcb[idx] = __float2bfloat16(Wfc[idx]);
    if (idx < (size_t)T_STEPS * BATCH * FEAT)
        g_xb[idx] = __float2bfloat16(x[idx]);
}

// gx = x @ Wih^T + bsum, bf16. grid = 2048 row-tiles (64 rows), 256 threads.
__global__ void __launch_bounds__(256)
gx_kernel()
{
    extern __shared__ char gs[];
    __nv_bfloat16* Ax = reinterpret_cast<__nv_bfloat16*>(gs);            // 64 x 104
    __nv_bfloat16* Bw = Ax + 64 * 104;                                   // 256 x 104

    const int tid  = threadIdx.x;
    const int lane = tid & 31, wid = tid >> 5;
    const int r0   = blockIdx.x * 64;
    const int rowt = (wid & 3) * 16;
    const int colg = (wid >> 2) * 128;

    const unsigned ax_u = smem_u32(Ax);
    const unsigned bw_u = smem_u32(Bw);

    for (int i = tid; i < 64 * 4; i += 256)
        reinterpret_cast<unsigned*>(Ax)[(i >> 2) * 52 + 44 + (i & 3)] = 0u;
    for (int i = tid; i < 64 * 11; i += 256) {
        int row = i / 11, seg = i % 11;
        unsigned dst = ax_u + (unsigned)((row * 104 + seg * 8) * 2);
        CP_ASYNC16(dst, g_xb + (size_t)(r0 + row) * FEAT + seg * 8);
    }
    CP_COMMIT;

    for (int ci = 0; ci < 16; ++ci) {
        const int c0 = ci * 256;
        for (int i = tid; i < 256 * 12; i += 256) {
            int row = i / 12, seg = i % 12;
            unsigned dst = bw_u + (unsigned)((row * 104 + seg * 8) * 2);
            CP_ASYNC16(dst, g_Wxb + (size_t)(c0 + row) * 96 + seg * 8);
        }
        CP_COMMIT;
        CP_WAIT(0);
        __syncthreads();

        float acc[16][4];
#pragma unroll
        for (int i = 0; i < 16; ++i)
#pragma unroll
            for (int j = 0; j < 4; ++j) acc[i][j] = 0.f;

#pragma unroll
        for (int ks = 0; ks < 6; ++ks) {
            int kk = ks * 16;
            unsigned a0, a1, a2, a3;
            unsigned addr = ax_u +
                (unsigned)(((rowt + (lane & 15)) * 104 + kk + ((lane >> 4) << 3)) * 2);
            LDMATRIX_X4(a0, a1, a2, a3, addr);
#pragma unroll
            for (int nf = 0; nf < 16; ++nf) {
                int n = colg + nf * 8 + (lane >> 2);
                unsigned baddr = bw_u + (unsigned)((n * 104 + kk + ((lane & 3) << 1)) * 2);
                unsigned b0r, b1r;
                asm volatile("ld.shared.b32 %0, [%1];" : "=r"(b0r) : "r"(baddr));
                asm volatile("ld.shared.b32 %0, [%1];" : "=r"(b1r) : "r"(baddr + 16));
                MMA_BF16(acc[nf], a0, a1, a2, a3, b0r, b1r);
            }
        }
        __syncthreads();

#pragma unroll
        for (int half = 0; half < 2; ++half) {
            int r = rowt + (lane >> 2) + half * 8;
            size_t rbase = (size_t)(r0 + r) * 4096;
#pragma unroll
            for (int nf = 0; nf < 16; ++nf) {
                int c = c0 + colg + nf * 8 + ((lane & 3) << 1);
                float v0 = acc[nf][half * 2 + 0] + __ldg(g_bsum + c);
                float v1 = acc[nf][half * 2 + 1] + __ldg(g_bsum + c + 1);
                __nv_bfloat162 b2 = __floats2bfloat162_rn(v0, v1);
                *reinterpret_cast<unsigned*>(&g_gx[rbase + c]) =
                    *reinterpret_cast<unsigned*>(&b2);
            }
        }
    }
}

// ---------------- persistent LSTM kernel ----------------
// R13 chassis; NEW: W-column permutation maps each thread's acc quad to the
// 4 gates of ONE unit -> LSTM cell fully in registers (no gsm exchange, 2
// fewer syncthreads); balanced warp<->row-block map {0,48}/{16,32}; frozen-row
// store elision.
// SMEM col c (0..63): warp wn = c>>4, within c16 = c&15 = 8nf+2q+e
//   -> gate g = e + 2nf = (c&1) + 2*((c>>3)&1), unit u = 4*wn + ((c>>1)&3).
__global__ void __launch_bounds__(NTHR, 1)
lstm_kernel(const int* __restrict__ lens)
{
    extern __shared__ char smem_raw[];
    __nv_bfloat16* Ws  = reinterpret_cast<__nv_bfloat16*>(smem_raw);        // 64 * WS_STRIDE
    __nv_bfloat16* As  = Ws + 64 * WS_STRIDE;                               // NBUF * 64 * ASTR
    __nv_bfloat16* Gb  = As + NBUF * 64 * ASTR;                             // 64 * GBSTR
    int*   len_s       = reinterpret_cast<int*>(Gb + 64 * GBSTR);           // 64

    const int tid   = threadIdx.x;
    const int bid   = blockIdx.x;
    const int cta_m = bid & 1;
    const int cta_n = bid >> 1;
    const int b0    = cta_m * MT;
    const int hid0  = cta_n * UPC;

    // resident W slice with (gate,unit) column permutation + k-pair permutation
    for (int i = tid; i < 64 * (HID / 2); i += NTHR) {
        int n = i / (HID / 2), j = i % (HID / 2);
        int g16 = j >> 3, q = j & 7;
        int sp  = (q >> 1) + ((q & 1) << 2);
        int g = (n & 1) + 2 * ((n >> 3) & 1);
        int u = 4 * (n >> 4) + ((n >> 1) & 3);
        const unsigned* src = reinterpret_cast<const unsigned*>(
                g_Wc + (size_t)(g * HID + hid0 + u) * HID);
        reinterpret_cast<unsigned*>(Ws + (size_t)n * WS_STRIDE)[j] = src[g16 * 8 + sp];
    }
    if (tid < 64) len_s[tid] = lens[b0 + tid];
    __syncthreads();

    const int lane = tid & 31, wid = tid >> 5;
    const int wm = wid & 1;        // 0..1
    const int wn = wid >> 1;       // 0..3 : units 4wn..4wn+3
    const int u_loc = 4 * wn + (lane & 3);

    // balanced row blocks: wm0 -> {0, 48}, wm1 -> {16, 32}
    const int rb0 = 16 * wm;
    const int rb1 = 48 - 16 * wm;

    const unsigned ws_u = smem_u32(Ws);
    const unsigned as_u = smem_u32(As);
    const unsigned gb_u = smem_u32(Gb);

    const bool watcher = (tid < 64);
    int* const my_fp   = &g_flag[(((tid & 63) << 1) | cta_m) << 2];

    const int len0 = len_s[0];
    const int lt0  = len_s[rb0];               // tile mi=0 bound
    const int lt1  = len_s[rb1];               // tile mi=1 bound (<= lt0)

    // per-thread cell rows + lengths: li = 2*mi + half
    int rown[4], lenr[4];
#pragma unroll
    for (int mi = 0; mi < 2; ++mi)
#pragma unroll
        for (int h2 = 0; h2 < 2; ++h2) {
            int r = (mi == 0 ? rb0 : rb1) + (lane >> 2) + 8 * h2;
            rown[2 * mi + h2] = r;
            lenr[2 * mi + h2] = len_s[r];
        }

    float hreg[4] = {0.f, 0.f, 0.f, 0.f};
    float creg[4] = {0.f, 0.f, 0.f, 0.f};

    for (int t = 0; t < T_STEPS; ++t) {
        const __nv_bfloat16* __restrict__ h_cur = g_h[t & 1];
        __nv_bfloat16* __restrict__ h_nxt = g_h[(t & 1) ^ 1];

        // whole-CTA early exit: all rows of this half frozen (dead stores dropped)
        if (t >= len0) {
            if (tid == 0) {
                asm volatile("membar.gl;" ::: "memory");
                __stcg(&g_flag[bid << 2], T_STEPS);
            }
            CP_WAIT(0);
            break;
        }

        // stage gx slice for step t (h-independent, pre-barrier)
        {
#pragma unroll
            for (int r = 0; r < 2; ++r) {
                int slot = tid + r * NTHR;          // 0..511 = 64 rows x 8 segs
                int row = slot >> 3, seg = slot & 7;
                int g = seg >> 1, half8 = seg & 1;
                unsigned dst = gb_u + (unsigned)((row * GBSTR + g * 16 + half8 * 8) * 2);
                CP_ASYNC16(dst, g_gx + ((size_t)t * BATCH + b0 + row) * 4096 +
                                g * HID + hid0 + half8 * 8);
            }
            CP_COMMIT;
        }

        // half-barrier: 64 same-half CTAs have published step t-1
        if (t > 0) {
            int fv = 0x7fffffff;
            if (watcher)
                asm volatile("ld.acquire.gpu.global.b32 %0, [%1];" : "=r"(fv) : "l"(my_fp) : "memory");
            for (;;) {
                if (__syncthreads_count(fv >= t) == NTHR) break;
                if (watcher && fv < t)
                    asm volatile("ld.acquire.gpu.global.b32 %0, [%1];" : "=r"(fv) : "l"(my_fp) : "memory");
            }
        }

        auto stage = [&](int s) {
            unsigned dstb = as_u + (unsigned)((s & 3) * 64 * ASTR * 2);
#pragma unroll
            for (int r = 0; r < 4; ++r) {
                int slot = tid + r * NTHR;          // 1024 slots = 64 rows x 16 seg
                int row = slot >> 4, c16 = slot & 15;
                unsigned dst = dstb + (unsigned)((row * ASTR + c16 * 8) * 2);
                CP_ASYNC16(dst, h_cur + (size_t)(b0 + row) * HID + (s - 1) * CW + c16 * 8);
            }
            CP_COMMIT;
        };

        stage(1);
        stage(2);
        stage(3);

        float acc[2][2][4];
#pragma unroll
        for (int a = 0; a < 2; ++a)
#pragma unroll
            for (int b = 0; b < 2; ++b)
#pragma unroll
                for (int c = 0; c < 4; ++c) acc[a][b][c] = 0.f;

        const bool act1 = (t < lt1);
        const bool act0 = (t < lt0);

#pragma unroll
        for (int s = 1; s <= 8; ++s) {
            if (s <= 6)      { CP_WAIT(2); }
            else if (s == 7) { CP_WAIT(1); }
            else             { CP_WAIT(0); }
            __syncthreads();
            if (s + 3 <= 8) stage(s + 3);

            const int kcol = (s - 1) * CW;
            const unsigned abase = as_u + (unsigned)((s & 3) * 64 * ASTR * 2);

            if (act1) {
#pragma unroll
                for (int ks = 0; ks < 8; ++ks) {
                    const int kk = ks * 16;
                    const int kg = kcol + kk;
                    unsigned a0r[4], a1r[4], bfr[2][2];
                    unsigned addr0 = abase +
                        (unsigned)(((rb0 + (lane & 15)) * ASTR + kk + ((lane >> 4) << 3)) * 2);
                    LDMATRIX_X4(a0r[0], a0r[1], a0r[2], a0r[3], addr0);
                    LDMATRIX_X4(a1r[0], a1r[1], a1r[2], a1r[3],
                                addr0 + (unsigned)((rb1 - rb0) * ASTR * 2));
#pragma unroll
                    for (int nf = 0; nf < 2; ++nf) {
                        int n = wn * 16 + nf * 8 + (lane >> 2);
                        unsigned baddr = ws_u +
                            (unsigned)((n * WS_STRIDE + kg) * 2) + ((lane & 3) << 3);
                        LDS64(bfr[nf][0], bfr[nf][1], baddr);
                        MMA_BF16(acc[0][nf], a0r[0], a0r[1], a0r[2], a0r[3], bfr[nf][0], bfr[nf][1]);
                        MMA_BF16(acc[1][nf], a1r[0], a1r[1], a1r[2], a1r[3], bfr[nf][0], bfr[nf][1]);
                    }
                }
            } else if (act0) {
#pragma unroll
                for (int ks = 0; ks < 8; ++ks) {
                    const int kk = ks * 16;
                    const int kg = kcol + kk;
                    unsigned a0r[4], bfr[2][2];
                    unsigned addr0 = abase +
                        (unsigned)(((rb0 + (lane & 15)) * ASTR + kk + ((lane >> 4) << 3)) * 2);
                    LDMATRIX_X4(a0r[0], a0r[1], a0r[2], a0r[3], addr0);
#pragma unroll
                    for (int nf = 0; nf < 2; ++nf) {
                        int n = wn * 16 + nf * 8 + (lane >> 2);
                        unsigned baddr = ws_u +
                            (unsigned)((n * WS_STRIDE + kg) * 2) + ((lane & 3) << 3);
                        LDS64(bfr[nf][0], bfr[nf][1], baddr);
                        MMA_BF16(acc[0][nf], a0r[0], a0r[1], a0r[2], a0r[3], bfr[nf][0], bfr[nf][1]);
                    }
                }
            }
        }
        // NO exchange: cell directly from acc (each thread owns 4 gates of unit u_loc)

        __nv_bfloat16 hb[4];
#pragma unroll
        for (int mi = 0; mi < 2; ++mi)
#pragma unroll
            for (int h2 = 0; h2 < 2; ++h2) {
                const int li = 2 * mi + h2;
                const int r  = rown[li];
                float gi = acc[mi][0][2 * h2]     + __bfloat162float(Gb[r * GBSTR + u_loc]);
                float gf = acc[mi][0][2 * h2 + 1] + __bfloat162float(Gb[r * GBSTR + 16 + u_loc]);
                float gg = acc[mi][1][2 * h2]     + __bfloat162float(Gb[r * GBSTR + 32 + u_loc]);
                float go = acc[mi][1][2 * h2 + 1] + __bfloat162float(Gb[r * GBSTR + 48 + u_loc]);
                float ii = sigmoidf_(gi);
                float ff = sigmoidf_(gf);
                float gt = tanhf_(gg);
                float oo = sigmoidf_(go);
                float cn = ff * creg[li] + ii * gt;
                float hn = oo * tanhf_(cn);
                bool  m  = t < lenr[li];
                float h2v = m ? hn : hreg[li];
                creg[li] = m ? cn : creg[li];
                hreg[li] = h2v;
                hb[li] = __float2bfloat16(h2v);
                if (t <= lenr[li])           // settle both parities, then skip
                    h_nxt[(b0 + r) * HID + hid0 + u_loc] = hb[li];
            }

        // publish step t: one barrier, tid0 gpu fence + flag store
        __syncthreads();
        if (tid == 0) {
            asm volatile("membar.gl;" ::: "memory");
            __stcg(&g_flag[bid << 2], t + 1);
        }

        // g_Hall: only needed for t < len (fc zeroes masked rows) -> off critical path
#pragma unroll
        for (int li = 0; li < 4; ++li) {
            if (t < lenr[li]) {
                int r = rown[li];
                g_Hall[((size_t)t * BATCH + b0 + r) * HID + hid0 + u_loc] = hb[li];
            }
        }
    }
}

// ---------------- FC head: logits + binary expansion ----------------
__global__ void __launch_bounds__(128)
fc_kernel(const int* __restrict__ lens, const float* __restrict__ bfc,
          float* __restrict__ out)
{
    __shared__ __nv_bfloat16 As[64 * FC_ASTR];
    __shared__ __nv_bfloat16 Bs[88 * FC_ASTR];

    const int tid  = threadIdx.x;
    const int lane = tid & 31, wid = tid >> 5;
    const int r0   = blockIdx.x * 64;

    float acc[11][4];
#pragma unroll
    for (int i = 0; i < 11; ++i)
#pragma unroll
        for (int j = 0; j < 4; ++j) acc[i][j] = 0.f;

    const unsigned as_u = smem_u32(As);
    const unsigned bs_u = smem_u32(Bs);

    for (int ch = 0; ch < 16; ++ch) {
        __syncthreads();
        const int k0 = ch * 64;
        for (int i = tid; i < 512; i += 128) {
            int row = i >> 3, c8 = i & 7;
            uint4 v = *(reinterpret_cast<const uint4*>(
                    g_Hall + (size_t)(r0 + row) * HID + k0) + c8);
            *(reinterpret_cast<uint4*>(As + row * FC_ASTR) + c8) = v;
        }
        for (int i = tid; i < 704; i += 128) {
            int row = i >> 3, c8 = i & 7;
            uint4 v = *(reinterpret_cast<const uint4*>(
                    g_Wfcb + (size_t)row * HID + k0) + c8);
            *(reinterpret_cast<uint4*>(Bs + row * FC_ASTR) + c8) = v;
        }
        __syncthreads();
#pragma unroll
        for (int ks = 0; ks < 4; ++ks) {
            int kk = ks * 16;
            unsigned a0, a1, a2, a3;
            unsigned addr = as_u +
                (unsigned)(((wid * 16 + (lane & 15)) * FC_ASTR + kk + ((lane >> 4) << 3)) * 2);
            LDMATRIX_X4(a0, a1, a2, a3, addr);
#pragma unroll
            for (int nf = 0; nf < 11; ++nf) {
                int n = nf * 8 + (lane >> 2);
                unsigned baddr = bs_u +
                    (unsigned)((n * FC_ASTR + kk + ((lane & 3) << 1)) * 2);
                unsigned b0r, b1r;
                asm volatile("ld.shared.b32 %0, [%1];" : "=r"(b0r) : "r"(baddr));
                asm volatile("ld.shared.b32 %0, [%1];" : "=r"(b1r) : "r"(baddr + 16));
                MMA_BF16(acc[nf], a0, a1, a2, a3, b0r, b1r);
            }
        }
    }

#pragma unroll
    for (int half = 0; half < 2; ++half) {
        int r  = wid * 16 + (lane >> 2) + half * 8;
        int tb = r0 + r;
        int t  = tb >> 7;
        int b  = tb & 127;
        bool m = t < __ldg(lens + b);
        size_t obase = ((size_t)b * T_STEPS + t) * CLS * 2;
#pragma unroll
        for (int nf = 0; nf < 11; ++nf) {
            int c = nf * 8 + ((lane & 3) << 1);
            float l0 = acc[nf][half * 2 + 0] + __ldg(bfc + c);
            float l1 = acc[nf][half * 2 + 1] + __ldg(bfc + c + 1);
            if (!m) { l0 = 0.f; l1 = 0.f; }
            float4 v = make_float4(l0, 1.f - l0, l1, 1.f - l1);
            *reinterpret_cast<float4*>(out + obase + (size_t)c * 2) = v;
        }
    }
}

// ---------------- launch ----------------
extern "C" void kernel_launch(void* const* d_in, const int* in_sizes, int n_in,
                              void* d_out, int out_size) {
    const float* x    = (const float*)d_in[0];
    const int*   lens = (const int*)d_in[1];    // int32 (JAX x64 disabled)
    const float* Wih  = (const float*)d_in[2];
    const float* Whh  = (const float*)d_in[3];
    const float* bih  = (const float*)d_in[4];
    const float* bhh  = (const float*)d_in[5];
    const float* Wfc  = (const float*)d_in[6];
    const float* bfc  = (const float*)d_in[7];
    float*       out  = (float*)d_out;
    (void)in_sizes; (void)n_in; (void)out_size;

    // launch order: init(1), prep_all(2), gx(3), lstm(4 = ncu slot), fc(5)
    init_kernel<<<64, 256>>>();
    {
        size_t tot = (size_t)T_STEPS * BATCH * FEAT;
        prep_all_kernel<<<(unsigned)((tot + 255) / 256), 256>>>(x, Wih, Whh, bih, bhh, Wfc);
    }
    {
        int gx_smem = (64 * 104 + 256 * 104) * 2;      // 66,560 B
        cudaFuncSetAttribute(gx_kernel, cudaFuncAttributeMaxDynamicSharedMemorySize, gx_smem);
        gx_kernel<<<(T_STEPS * BATCH) / 64, 256, gx_smem>>>();
    }

    int smem = 64 * WS_STRIDE * 2          // resident W slice   (132,096)
             + NBUF * 64 * ASTR * 2        // A-stage ring       (69,632)
             + 64 * GBSTR * 2              // gx slice           (9,216)
             + 64 * 4;                     // lengths
    cudaFuncSetAttribute(lstm_kernel, cudaFuncAttributeMaxDynamicSharedMemorySize, smem);
    lstm_kernel<<<NCTA, NTHR, smem>>>(lens);

    fc_kernel<<<(T_STEPS * BATCH) / 64, 128>>>(lens, bfc, out);
}